// round 10
// baseline (speedup 1.0000x reference)
#include <cuda_runtime.h>
#include <cstdint>

#define BB   32
#define TQQ  2000
#define TKK  512
#define EXNEG (-2000000)
#define PBLANK 0.36787944117144233f   /* e^-1 */
#define L2E 1.4426950408889634f
#define FULLW 0xffffffffu

__device__ float    g_loss[BB];
__device__ float    g_logz[BB * TQQ];
__device__ unsigned g_ctr = 0;

__device__ __forceinline__ float ex2f_(float x) {
    float r; asm("ex2.approx.ftz.f32 %0, %1;" : "=f"(r) : "f"(x)); return r;
}
__device__ __forceinline__ unsigned smem_u32(const void* p) {
    unsigned r;
    asm("{.reg .u64 t; cvta.to.shared.u64 t, %1; cvt.u32.u64 %0, t;}" : "=r"(r) : "l"(p));
    return r;
}
__device__ __forceinline__ void st_rel_sh(unsigned a, int v) {
    asm volatile("st.release.cta.shared.b32 [%0], %1;" :: "r"(a), "r"(v) : "memory");
}
__device__ __forceinline__ int ld_acq_sh(unsigned a) {
    int v; asm volatile("ld.acquire.cta.shared.b32 %0, [%1];" : "=r"(v) : "r"(a) : "memory");
    return v;
}

// ---------------------------------------------------------------------------
// Kernel 1: per-row log partition  logZ = log(e^-1 + sum_{j<kl} exp(x))
// (identical to R4 — runs to completion before dp launches; NO overlap,
//  overlap provably poisons dp's L1tex queue)
// ---------------------------------------------------------------------------
__global__ __launch_bounds__(256) void zlog_kernel(const float* __restrict__ attn,
                                                   const int* __restrict__ in_lens,
                                                   const int* __restrict__ out_lens) {
    int b    = blockIdx.y;
    int warp = threadIdx.x >> 5;
    int lane = threadIdx.x & 31;
    int t    = blockIdx.x * 8 + warp;
    if (t >= TQQ) return;
    int kl = min(max(in_lens[b], 1), TKK);
    int ql = min(max(out_lens[b], 1), TQQ);
    if (t >= ql) return;

    const float4* row = (const float4*)(attn + ((size_t)b * TQQ + t) * TKK);
    float s = 0.f;
#pragma unroll
    for (int k = 0; k < 4; k++) {
        float4 v = __ldg(row + lane + 32 * k);
        int j = 4 * (lane + 32 * k);
        float a0 = (j + 0 < kl) ? __expf(v.x) : 0.f;
        float a1 = (j + 1 < kl) ? __expf(v.y) : 0.f;
        float a2 = (j + 2 < kl) ? __expf(v.z) : 0.f;
        float a3 = (j + 3 < kl) ? __expf(v.w) : 0.f;
        s += (a0 + a1) + (a2 + a3);
    }
#pragma unroll
    for (int o = 16; o; o >>= 1) s += __shfl_xor_sync(FULLW, s, o);
    if (lane == 0) g_logz[b * TQQ + t] = __logf(PBLANK + s);
}

// ---------------------------------------------------------------------------
// Kernel 2: CTC forward recursion, warp-skew pipeline (no block barrier in
// the serial loop). One block per batch, 128 threads; thread i owns states
// 8i..8i+7. Warp w consumes warp w-1's group-start boundary record via
// acquire/release flags in SMEM; warps free-run with natural skew.
// ---------------------------------------------------------------------------
__global__ __launch_bounds__(128, 1) void dp_kernel(const float* __restrict__ attn,
                                                    const int* __restrict__ in_lens,
                                                    const int* __restrict__ out_lens,
                                                    float* __restrict__ out) {
    __shared__ float4 xrec[4][32][4];  // [producer warp][ring slot][quad]
    __shared__ int    prog[4];         // groups published by warp w
    __shared__ int    consf[4];        // groups consumed by warp w
    __shared__ float  sm_even[513];
    __shared__ float  sm_odd[513];
    __shared__ int    sm_ex[513];
    __shared__ float  red[128];

    int b    = blockIdx.x;
    int tid  = threadIdx.x;
    int lane = tid & 31;
    int wid  = tid >> 5;
    int kl = min(max(in_lens[b], 1), TKK);
    int ql = min(max(out_lens[b], 1), TQQ);

    if (tid < 4) { prog[tid] = 0; consf[tid] = 0; }
    __syncthreads();

    const float4* base4 = (const float4*)(attn + (size_t)b * TQQ * TKK) + tid;

    bool mk0 = (tid * 4 + 0) < kl;
    bool mk1 = (tid * 4 + 1) < kl;
    bool mk2 = (tid * 4 + 2) < kl;
    bool mk3 = (tid * 4 + 3) < kl;

    unsigned prog_self_a  = smem_u32(&prog[wid]);
    unsigned prog_left_a  = smem_u32(&prog[wid > 0 ? wid - 1 : 0]);
    unsigned consf_self_a = smem_u32(&consf[wid]);
    unsigned consf_next_a = smem_u32(&consf[wid < 3 ? wid + 1 : 3]);

    // ---- row 0 init (B_0 = A_0) ----
    float4 x0 = __ldg(base4);
    float c8[8];
#pragma unroll
    for (int k = 0; k < 8; k++) c8[k] = 0.f;
    float a1024 = 0.f;
    int   exo   = EXNEG;
    if (tid == 0) { c8[0] = PBLANK; c8[1] = __expf(x0.x); exo = 0; }

    // ---- prefetch rows 1..8 ----
    int qm = ql - 1;
    float4 xs0 = __ldg(base4 + (size_t)min(1, qm) * 128);
    float4 xs1 = __ldg(base4 + (size_t)min(2, qm) * 128);
    float4 xs2 = __ldg(base4 + (size_t)min(3, qm) * 128);
    float4 xs3 = __ldg(base4 + (size_t)min(4, qm) * 128);
    float4 xs4 = __ldg(base4 + (size_t)min(5, qm) * 128);
    float4 xs5 = __ldg(base4 + (size_t)min(6, qm) * 128);
    float4 xs6 = __ldg(base4 + (size_t)min(7, qm) * 128);
    float4 xs7 = __ldg(base4 + (size_t)min(8, qm) * 128);

    int t  = 1;
    int gi = 0;

#define EMIT(XC, MK) ((MK) ? ex2f_(fmaf((XC), L2E, L2E)) : 0.f)
#define PAIRS(DST, SRC, J, EM)                                                 \
    { float se_ = SRC[J] + SRC[J - 1]; DST[J] = se_;                           \
      DST[J + 1] = (SRC[J + 1] + se_) * (EM); }

#define GROUP(S0, S1, S2, S3, REFILL, GUARDED)                                 \
    {                                                                          \
        float e00 = EMIT((S0).x, mk0), e01 = EMIT((S0).y, mk1);                \
        float e02 = EMIT((S0).z, mk2), e03 = EMIT((S0).w, mk3);                \
        float e10 = EMIT((S1).x, mk0), e11 = EMIT((S1).y, mk1);                \
        float e12 = EMIT((S1).z, mk2), e13 = EMIT((S1).w, mk3);                \
        float e20 = EMIT((S2).x, mk0), e21 = EMIT((S2).y, mk1);                \
        float e22 = EMIT((S2).z, mk2), e23 = EMIT((S2).w, mk3);                \
        float e30 = EMIT((S3).x, mk0), e31 = EMIT((S3).y, mk1);                \
        float e32 = EMIT((S3).z, mk2), e33 = EMIT((S3).w, mk3);                \
        int slot_ = gi & 31;                                                   \
        if (lane == 31) {                                                      \
            if (((gi & 15) == 0) && (wid < 3)) {                               \
                while (ld_acq_sh(consf_next_a) < gi - 16) { }                  \
            }                                                                  \
            float4* wb = &xrec[wid][slot_][0];                                 \
            wb[0] = make_float4(c8[0], c8[1], c8[2], c8[3]);                   \
            wb[1] = make_float4(c8[4], c8[5], c8[6], c8[7]);                   \
            wb[2] = make_float4(__int_as_float(exo), e01, e02, e03);           \
            wb[3] = make_float4(e12, e13, e23, 0.f);                           \
            st_rel_sh(prog_self_a, gi + 1);                                    \
        }                                                                      \
        if (REFILL) {                                                          \
            (S0) = __ldg(base4 + (size_t)min(t + 8,  qm) * 128);               \
            (S1) = __ldg(base4 + (size_t)min(t + 9,  qm) * 128);               \
            (S2) = __ldg(base4 + (size_t)min(t + 10, qm) * 128);               \
            (S3) = __ldg(base4 + (size_t)min(t + 11, qm) * 128);               \
        }                                                                      \
        float f01 = __shfl_up_sync(FULLW, e01, 1);                             \
        float f02 = __shfl_up_sync(FULLW, e02, 1);                             \
        float f03 = __shfl_up_sync(FULLW, e03, 1);                             \
        float f12 = __shfl_up_sync(FULLW, e12, 1);                             \
        float f13 = __shfl_up_sync(FULLW, e13, 1);                             \
        float f23 = __shfl_up_sync(FULLW, e23, 1);                             \
        float h_[8]; int he_;                                                  \
        h_[0] = __shfl_up_sync(FULLW, c8[0], 1);                               \
        h_[1] = __shfl_up_sync(FULLW, c8[1], 1);                               \
        h_[2] = __shfl_up_sync(FULLW, c8[2], 1);                               \
        h_[3] = __shfl_up_sync(FULLW, c8[3], 1);                               \
        h_[4] = __shfl_up_sync(FULLW, c8[4], 1);                               \
        h_[5] = __shfl_up_sync(FULLW, c8[5], 1);                               \
        h_[6] = __shfl_up_sync(FULLW, c8[6], 1);                               \
        h_[7] = __shfl_up_sync(FULLW, c8[7], 1);                               \
        he_  = __shfl_up_sync(FULLW, exo, 1);                                  \
        if (lane == 0) {                                                       \
            if (wid > 0) {                                                     \
                while (ld_acq_sh(prog_left_a) < gi + 1) { }                    \
                const float4* rb = &xrec[wid - 1][slot_][0];                   \
                float4 q0 = rb[0], q1 = rb[1], q2 = rb[2], q3 = rb[3];         \
                h_[0] = q0.x; h_[1] = q0.y; h_[2] = q0.z; h_[3] = q0.w;        \
                h_[4] = q1.x; h_[5] = q1.y; h_[6] = q1.z; h_[7] = q1.w;        \
                he_ = __float_as_int(q2.x);                                    \
                f01 = q2.y; f02 = q2.z; f03 = q2.w;                            \
                f12 = q3.x; f13 = q3.y; f23 = q3.z;                            \
                st_rel_sh(consf_self_a, gi + 1);                               \
            } else {                                                           \
                h_[0] = h_[1] = h_[2] = h_[3] = 0.f;                           \
                h_[4] = h_[5] = h_[6] = h_[7] = 0.f;                           \
                he_ = EXNEG;                                                   \
                f01 = f02 = f03 = f12 = f13 = f23 = 0.f;                       \
            }                                                                  \
        }                                                                      \
        int bse = max(exo, he_);                                               \
        int d0_ = 127 + (he_ - bse); if (d0_ < 0) d0_ = 0;                     \
        int d1_ = 127 + (exo - bse); if (d1_ < 0) d1_ = 0;                     \
        float sh_ = __int_as_float(d0_ << 23);                                 \
        float so_ = __int_as_float(d1_ << 23);                                 \
        float A_[16], B_[16];                                                  \
        A_[0] = h_[0] * sh_; A_[1] = h_[1] * sh_;                              \
        A_[2] = h_[2] * sh_; A_[3] = h_[3] * sh_;                              \
        A_[4] = h_[4] * sh_; A_[5] = h_[5] * sh_;                              \
        A_[6] = h_[6] * sh_; A_[7] = h_[7] * sh_;                              \
        A_[8]  = c8[0] * so_; A_[9]  = c8[1] * so_;                            \
        A_[10] = c8[2] * so_; A_[11] = c8[3] * so_;                            \
        A_[12] = c8[4] * so_; A_[13] = c8[5] * so_;                            \
        A_[14] = c8[6] * so_; A_[15] = c8[7] * so_;                            \
        float n4 = a1024 * so_;                                                \
        if (!(GUARDED) || (t + 0 < ql)) {                                      \
            PAIRS(B_, A_, 2, f01) PAIRS(B_, A_, 4, f02) PAIRS(B_, A_, 6, f03)  \
            PAIRS(B_, A_, 8, e00) PAIRS(B_, A_, 10, e01)                       \
            PAIRS(B_, A_, 12, e02) PAIRS(B_, A_, 14, e03)                      \
            n4 = n4 + A_[15];                                                  \
        } else {                                                               \
            _Pragma("unroll")                                                  \
            for (int j_ = 2; j_ < 16; j_++) B_[j_] = A_[j_];                   \
        }                                                                      \
        if (!(GUARDED) || (t + 1 < ql)) {                                      \
            PAIRS(A_, B_, 4, f12) PAIRS(A_, B_, 6, f13)                        \
            PAIRS(A_, B_, 8, e10) PAIRS(A_, B_, 10, e11)                       \
            PAIRS(A_, B_, 12, e12) PAIRS(A_, B_, 14, e13)                      \
            n4 = n4 + B_[15];                                                  \
        } else {                                                               \
            _Pragma("unroll")                                                  \
            for (int j_ = 4; j_ < 16; j_++) A_[j_] = B_[j_];                   \
        }                                                                      \
        if (!(GUARDED) || (t + 2 < ql)) {                                      \
            PAIRS(B_, A_, 6, f23)                                              \
            PAIRS(B_, A_, 8, e20) PAIRS(B_, A_, 10, e21)                       \
            PAIRS(B_, A_, 12, e22) PAIRS(B_, A_, 14, e23)                      \
            n4 = n4 + A_[15];                                                  \
        } else {                                                               \
            _Pragma("unroll")                                                  \
            for (int j_ = 6; j_ < 16; j_++) B_[j_] = A_[j_];                   \
        }                                                                      \
        if (!(GUARDED) || (t + 3 < ql)) {                                      \
            PAIRS(A_, B_, 8, e30) PAIRS(A_, B_, 10, e31)                       \
            PAIRS(A_, B_, 12, e32) PAIRS(A_, B_, 14, e33)                      \
            n4 = n4 + B_[15];                                                  \
        } else {                                                               \
            _Pragma("unroll")                                                  \
            for (int j_ = 8; j_ < 16; j_++) A_[j_] = B_[j_];                   \
        }                                                                      \
        float m_ = fmaxf(fmaxf(fmaxf(A_[8], A_[9]), fmaxf(A_[10], A_[11])),    \
                         fmaxf(fmaxf(A_[12], A_[13]), fmaxf(A_[14], A_[15]))); \
        m_ = fmaxf(m_, n4);                                                    \
        int kk_ = ((__float_as_int(m_) >> 23) & 255) - 127;                    \
        float sc_ = __int_as_float((127 - kk_) << 23);                         \
        c8[0] = A_[8]  * sc_; c8[1] = A_[9]  * sc_;                            \
        c8[2] = A_[10] * sc_; c8[3] = A_[11] * sc_;                            \
        c8[4] = A_[12] * sc_; c8[5] = A_[13] * sc_;                            \
        c8[6] = A_[14] * sc_; c8[7] = A_[15] * sc_;                            \
        a1024 = n4 * sc_;                                                      \
        exo = (m_ > 0.f) ? (bse + kk_) : EXNEG;                                \
        t += 4; gi++;                                                          \
    }

    while (t + 7 < ql) {
        GROUP(xs0, xs1, xs2, xs3, 1, 0)
        GROUP(xs4, xs5, xs6, xs7, 1, 0)
    }
    if (t + 3 < ql) {
        GROUP(xs0, xs1, xs2, xs3, 0, 0)
        if (t < ql) { GROUP(xs4, xs5, xs6, xs7, 0, 1) }
    } else if (t < ql) {
        GROUP(xs0, xs1, xs2, xs3, 0, 1)
    }

    // ---- epilogue ----
#pragma unroll
    for (int k = 0; k < 4; k++) {
        sm_even[tid * 4 + k] = c8[2 * k];
        sm_odd [tid * 4 + k] = c8[2 * k + 1];
        sm_ex  [tid * 4 + k] = exo;
    }
    if (tid == 127) { sm_even[512] = a1024; sm_odd[512] = 0.f; sm_ex[512] = exo; }

    __syncthreads();

    float lz = 0.f;
    for (int tt = tid; tt < ql; tt += 128) lz += g_logz[b * TQQ + tt];
    red[tid] = lz;
    __syncthreads();
#pragma unroll
    for (int s = 64; s; s >>= 1) {
        if (tid < s) red[tid] += red[tid + s];
        __syncthreads();
    }

    if (tid == 0) {
        float mE = sm_even[kl];     int eE = sm_ex[kl];       // state 2kl
        float mL = sm_odd[kl - 1];  int eL = sm_ex[kl - 1];   // state 2kl-1
        double ll;
        if (mE == 0.f && mL == 0.f) {
            ll = -1e9;
        } else {
            int eM = max(mE > 0.f ? eE : EXNEG, mL > 0.f ? eL : EXNEG);
            double s2 = 0.0;
            if (mE > 0.f) s2 += (double)mE * exp2((double)(eE - eM));
            if (mL > 0.f) s2 += (double)mL * exp2((double)(eL - eM));
            ll = log(s2) + (double)eM * 0.6931471805599453;
        }
        ll -= (double)red[0];          // - sum_t log Z_t
        ll -= (double)(ql - 1);        // undo B = A * e^t rescale
        g_loss[b] = (float)(-ll / (double)kl);

        __threadfence();
        unsigned prev = atomicAdd(&g_ctr, 1u);
        if (prev == BB - 1) {
            g_ctr = 0;
            __threadfence();
            float s = 0.f;
            for (int bb = 0; bb < BB; bb++) s += g_loss[bb];
            out[0] = s / (float)BB;
        }
    }
}

extern "C" void kernel_launch(void* const* d_in, const int* in_sizes, int n_in,
                              void* d_out, int out_size) {
    const float* attn     = (const float*)d_in[0];
    const int*   in_lens  = (const int*)d_in[1];
    const int*   out_lens = (const int*)d_in[2];

    zlog_kernel<<<dim3((TQQ + 7) / 8, BB), 256>>>(attn, in_lens, out_lens);
    dp_kernel<<<BB, 128>>>(attn, in_lens, out_lens, (float*)d_out);
}

// round 11
// speedup vs baseline: 8.3111x; 8.3111x over previous
#include <cuda_runtime.h>
#include <cstdint>

#define BB   32
#define TQQ  2000
#define TKK  512
#define EXNEG (-2000000)
#define PBLANK 0.36787944117144233f   /* e^-1 */
#define L2E 1.4426950408889634f
#define FULLW 0xffffffffu

__device__ float    g_loss[BB];
__device__ float    g_logz[BB * TQQ];
__device__ unsigned g_ctr = 0;

__device__ __forceinline__ float ex2f_(float x) {
    float r; asm("ex2.approx.ftz.f32 %0, %1;" : "=f"(r) : "f"(x)); return r;
}

// ---------------------------------------------------------------------------
// Kernel 1: per-row log partition  logZ = log(e^-1 + sum_{j<kl} exp(x))
// ---------------------------------------------------------------------------
__global__ __launch_bounds__(256) void zlog_kernel(const float* __restrict__ attn,
                                                   const int* __restrict__ in_lens,
                                                   const int* __restrict__ out_lens) {
    int b    = blockIdx.y;
    int warp = threadIdx.x >> 5;
    int lane = threadIdx.x & 31;
    int t    = blockIdx.x * 8 + warp;
    if (t >= TQQ) return;
    int kl = min(max(in_lens[b], 1), TKK);
    int ql = min(max(out_lens[b], 1), TQQ);
    if (t >= ql) return;

    const float4* row = (const float4*)(attn + ((size_t)b * TQQ + t) * TKK);
    float s = 0.f;
#pragma unroll
    for (int k = 0; k < 4; k++) {
        float4 v = __ldg(row + lane + 32 * k);
        int j = 4 * (lane + 32 * k);
        float a0 = (j + 0 < kl) ? __expf(v.x) : 0.f;
        float a1 = (j + 1 < kl) ? __expf(v.y) : 0.f;
        float a2 = (j + 2 < kl) ? __expf(v.z) : 0.f;
        float a3 = (j + 3 < kl) ? __expf(v.w) : 0.f;
        s += (a0 + a1) + (a2 + a3);
    }
#pragma unroll
    for (int o = 16; o; o >>= 1) s += __shfl_xor_sync(FULLW, s, o);
    if (lane == 0) g_logz[b * TQQ + t] = __logf(PBLANK + s);
}

// ---------------------------------------------------------------------------
// Kernel 2: CTC forward recursion. B-domain (blank folded out), 4 steps per
// exchange/barrier (lockstep — proven fastest), per-thread block floating
// point, 8-row prefetch. 128 threads; thread i owns states 8i..8i+7.
// Final mean over batches folded into the last-arriving block.
// ---------------------------------------------------------------------------
__global__ __launch_bounds__(128, 1) void dp_kernel(const float* __restrict__ attn,
                                                    const int* __restrict__ in_lens,
                                                    const int* __restrict__ out_lens,
                                                    float* __restrict__ out) {
    __shared__ float xch[2][5][16];   // [parity][warp+1][slot] slot0 = zeros
    __shared__ float sm_even[513];
    __shared__ float sm_odd[513];
    __shared__ int   sm_ex[513];
    __shared__ float red[128];

    int b    = blockIdx.x;
    int tid  = threadIdx.x;
    int lane = tid & 31;
    int warp = tid >> 5;
    int kl = min(max(in_lens[b], 1), TKK);
    int ql = min(max(out_lens[b], 1), TQQ);

    const float4* base4 = (const float4*)(attn + (size_t)b * TQQ * TKK) + tid;

    bool mk0 = (tid * 4 + 0) < kl;
    bool mk1 = (tid * 4 + 1) < kl;
    bool mk2 = (tid * 4 + 2) < kl;
    bool mk3 = (tid * 4 + 3) < kl;

    if (tid < 2) {
#pragma unroll
        for (int k = 0; k < 16; k++) xch[tid][0][k] = 0.f;
        xch[tid][0][8] = __int_as_float(EXNEG);
    }

    // ---- row 0 init (B_0 = A_0) ----
    float4 x0 = __ldg(base4);
    float c8[8];
#pragma unroll
    for (int k = 0; k < 8; k++) c8[k] = 0.f;
    float a1024 = 0.f;
    int   exo   = EXNEG;
    if (tid == 0) { c8[0] = PBLANK; c8[1] = __expf(x0.x); exo = 0; }

    // ---- prefetch rows 1..8 ----
    int qm = ql - 1;
    float4 xs0 = __ldg(base4 + (size_t)min(1, qm) * 128);
    float4 xs1 = __ldg(base4 + (size_t)min(2, qm) * 128);
    float4 xs2 = __ldg(base4 + (size_t)min(3, qm) * 128);
    float4 xs3 = __ldg(base4 + (size_t)min(4, qm) * 128);
    float4 xs4 = __ldg(base4 + (size_t)min(5, qm) * 128);
    float4 xs5 = __ldg(base4 + (size_t)min(6, qm) * 128);
    float4 xs6 = __ldg(base4 + (size_t)min(7, qm) * 128);
    float4 xs7 = __ldg(base4 + (size_t)min(8, qm) * 128);

    int t = 1;

#define EMIT(XC, MK) ((MK) ? ex2f_(fmaf((XC), L2E, L2E)) : 0.f)
#define PAIRS(DST, SRC, J, EM)                                                 \
    { float se_ = SRC[J] + SRC[J - 1]; DST[J] = se_;                           \
      DST[J + 1] = (SRC[J + 1] + se_) * (EM); }

#define GROUP(S0, S1, S2, S3, REFILL, GUARDED)                                 \
    {                                                                          \
        float e00 = EMIT((S0).x, mk0), e01 = EMIT((S0).y, mk1);                \
        float e02 = EMIT((S0).z, mk2), e03 = EMIT((S0).w, mk3);                \
        float e10 = EMIT((S1).x, mk0), e11 = EMIT((S1).y, mk1);                \
        float e12 = EMIT((S1).z, mk2), e13 = EMIT((S1).w, mk3);                \
        float e20 = EMIT((S2).x, mk0), e21 = EMIT((S2).y, mk1);                \
        float e22 = EMIT((S2).z, mk2), e23 = EMIT((S2).w, mk3);                \
        float e30 = EMIT((S3).x, mk0), e31 = EMIT((S3).y, mk1);                \
        float e32 = EMIT((S3).z, mk2), e33 = EMIT((S3).w, mk3);                \
        if (REFILL) {                                                          \
            (S0) = __ldg(base4 + (size_t)min(t + 8,  qm) * 128);               \
            (S1) = __ldg(base4 + (size_t)min(t + 9,  qm) * 128);               \
            (S2) = __ldg(base4 + (size_t)min(t + 10, qm) * 128);               \
            (S3) = __ldg(base4 + (size_t)min(t + 11, qm) * 128);               \
        }                                                                      \
        int p_ = ((t - 1) >> 2) & 1;                                           \
        if (lane == 31) {                                                      \
            float* wb = xch[p_][warp + 1];                                     \
            wb[0] = c8[0]; wb[1] = c8[1]; wb[2] = c8[2]; wb[3] = c8[3];        \
            wb[4] = c8[4]; wb[5] = c8[5]; wb[6] = c8[6]; wb[7] = c8[7];        \
            wb[8] = __int_as_float(exo);                                       \
            wb[9] = e01; wb[10] = e02; wb[11] = e03;                           \
            wb[12] = e12; wb[13] = e13; wb[14] = e23;                          \
        }                                                                      \
        __syncthreads();                                                       \
        float h_[8]; int he_;                                                  \
        float f01, f02, f03, f12, f13, f23;                                    \
        h_[0] = __shfl_up_sync(FULLW, c8[0], 1);                               \
        h_[1] = __shfl_up_sync(FULLW, c8[1], 1);                               \
        h_[2] = __shfl_up_sync(FULLW, c8[2], 1);                               \
        h_[3] = __shfl_up_sync(FULLW, c8[3], 1);                               \
        h_[4] = __shfl_up_sync(FULLW, c8[4], 1);                               \
        h_[5] = __shfl_up_sync(FULLW, c8[5], 1);                               \
        h_[6] = __shfl_up_sync(FULLW, c8[6], 1);                               \
        h_[7] = __shfl_up_sync(FULLW, c8[7], 1);                               \
        he_  = __shfl_up_sync(FULLW, exo, 1);                                  \
        f01 = __shfl_up_sync(FULLW, e01, 1);                                   \
        f02 = __shfl_up_sync(FULLW, e02, 1);                                   \
        f03 = __shfl_up_sync(FULLW, e03, 1);                                   \
        f12 = __shfl_up_sync(FULLW, e12, 1);                                   \
        f13 = __shfl_up_sync(FULLW, e13, 1);                                   \
        f23 = __shfl_up_sync(FULLW, e23, 1);                                   \
        if (lane == 0) {                                                       \
            const float* rb = xch[p_][warp];                                   \
            h_[0] = rb[0]; h_[1] = rb[1]; h_[2] = rb[2]; h_[3] = rb[3];        \
            h_[4] = rb[4]; h_[5] = rb[5]; h_[6] = rb[6]; h_[7] = rb[7];        \
            he_ = __float_as_int(rb[8]);                                       \
            f01 = rb[9]; f02 = rb[10]; f03 = rb[11];                           \
            f12 = rb[12]; f13 = rb[13]; f23 = rb[14];                          \
        }                                                                      \
        int bse = max(exo, he_);                                               \
        int d0_ = 127 + (he_ - bse); if (d0_ < 0) d0_ = 0;                     \
        int d1_ = 127 + (exo - bse); if (d1_ < 0) d1_ = 0;                     \
        float sh_ = __int_as_float(d0_ << 23);                                 \
        float so_ = __int_as_float(d1_ << 23);                                 \
        float A_[16], B_[16];                                                  \
        A_[0] = h_[0] * sh_; A_[1] = h_[1] * sh_;                              \
        A_[2] = h_[2] * sh_; A_[3] = h_[3] * sh_;                              \
        A_[4] = h_[4] * sh_; A_[5] = h_[5] * sh_;                              \
        A_[6] = h_[6] * sh_; A_[7] = h_[7] * sh_;                              \
        A_[8]  = c8[0] * so_; A_[9]  = c8[1] * so_;                            \
        A_[10] = c8[2] * so_; A_[11] = c8[3] * so_;                            \
        A_[12] = c8[4] * so_; A_[13] = c8[5] * so_;                            \
        A_[14] = c8[6] * so_; A_[15] = c8[7] * so_;                            \
        float n4 = a1024 * so_;                                                \
        if (!(GUARDED) || (t + 0 < ql)) {                                      \
            PAIRS(B_, A_, 2, f01) PAIRS(B_, A_, 4, f02) PAIRS(B_, A_, 6, f03)  \
            PAIRS(B_, A_, 8, e00) PAIRS(B_, A_, 10, e01)                       \
            PAIRS(B_, A_, 12, e02) PAIRS(B_, A_, 14, e03)                      \
            n4 = n4 + A_[15];                                                  \
        } else {                                                               \
            _Pragma("unroll")                                                  \
            for (int j_ = 2; j_ < 16; j_++) B_[j_] = A_[j_];                   \
        }                                                                      \
        if (!(GUARDED) || (t + 1 < ql)) {                                      \
            PAIRS(A_, B_, 4, f12) PAIRS(A_, B_, 6, f13)                        \
            PAIRS(A_, B_, 8, e10) PAIRS(A_, B_, 10, e11)                       \
            PAIRS(A_, B_, 12, e12) PAIRS(A_, B_, 14, e13)                      \
            n4 = n4 + B_[15];                                                  \
        } else {                                                               \
            _Pragma("unroll")                                                  \
            for (int j_ = 4; j_ < 16; j_++) A_[j_] = B_[j_];                   \
        }                                                                      \
        if (!(GUARDED) || (t + 2 < ql)) {                                      \
            PAIRS(B_, A_, 6, f23)                                              \
            PAIRS(B_, A_, 8, e20) PAIRS(B_, A_, 10, e21)                       \
            PAIRS(B_, A_, 12, e22) PAIRS(B_, A_, 14, e23)                      \
            n4 = n4 + A_[15];                                                  \
        } else {                                                               \
            _Pragma("unroll")                                                  \
            for (int j_ = 6; j_ < 16; j_++) B_[j_] = A_[j_];                   \
        }                                                                      \
        if (!(GUARDED) || (t + 3 < ql)) {                                      \
            PAIRS(A_, B_, 8, e30) PAIRS(A_, B_, 10, e31)                       \
            PAIRS(A_, B_, 12, e32) PAIRS(A_, B_, 14, e33)                      \
            n4 = n4 + B_[15];                                                  \
        } else {                                                               \
            _Pragma("unroll")                                                  \
            for (int j_ = 8; j_ < 16; j_++) A_[j_] = B_[j_];                   \
        }                                                                      \
        float m_ = fmaxf(fmaxf(fmaxf(A_[8], A_[9]), fmaxf(A_[10], A_[11])),    \
                         fmaxf(fmaxf(A_[12], A_[13]), fmaxf(A_[14], A_[15]))); \
        m_ = fmaxf(m_, n4);                                                    \
        int kk_ = ((__float_as_int(m_) >> 23) & 255) - 127;                    \
        float sc_ = __int_as_float((127 - kk_) << 23);                         \
        c8[0] = A_[8]  * sc_; c8[1] = A_[9]  * sc_;                            \
        c8[2] = A_[10] * sc_; c8[3] = A_[11] * sc_;                            \
        c8[4] = A_[12] * sc_; c8[5] = A_[13] * sc_;                            \
        c8[6] = A_[14] * sc_; c8[7] = A_[15] * sc_;                            \
        a1024 = n4 * sc_;                                                      \
        exo = (m_ > 0.f) ? (bse + kk_) : EXNEG;                                \
        t += 4;                                                                \
    }

    while (t + 7 < ql) {
        GROUP(xs0, xs1, xs2, xs3, 1, 0)
        GROUP(xs4, xs5, xs6, xs7, 1, 0)
    }
    if (t + 3 < ql) {
        GROUP(xs0, xs1, xs2, xs3, 0, 0)
        if (t < ql) { GROUP(xs4, xs5, xs6, xs7, 0, 1) }
    } else if (t < ql) {
        GROUP(xs0, xs1, xs2, xs3, 0, 1)
    }

    // ---- epilogue ----
#pragma unroll
    for (int k = 0; k < 4; k++) {
        sm_even[tid * 4 + k] = c8[2 * k];
        sm_odd [tid * 4 + k] = c8[2 * k + 1];
        sm_ex  [tid * 4 + k] = exo;
    }
    if (tid == 127) { sm_even[512] = a1024; sm_odd[512] = 0.f; sm_ex[512] = exo; }

    float lz = 0.f;
    for (int tt = tid; tt < ql; tt += 128) lz += g_logz[b * TQQ + tt];
    red[tid] = lz;
    __syncthreads();
#pragma unroll
    for (int s = 64; s; s >>= 1) {
        if (tid < s) red[tid] += red[tid + s];
        __syncthreads();
    }

    if (tid == 0) {
        float mE = sm_even[kl];     int eE = sm_ex[kl];       // state 2kl
        float mL = sm_odd[kl - 1];  int eL = sm_ex[kl - 1];   // state 2kl-1
        double ll;
        if (mE == 0.f && mL == 0.f) {
            ll = -1e9;
        } else {
            int eM = max(mE > 0.f ? eE : EXNEG, mL > 0.f ? eL : EXNEG);
            double s2 = 0.0;
            if (mE > 0.f) s2 += (double)mE * exp2((double)(eE - eM));
            if (mL > 0.f) s2 += (double)mL * exp2((double)(eL - eM));
            ll = log(s2) + (double)eM * 0.6931471805599453;
        }
        ll -= (double)red[0];          // - sum_t log Z_t
        ll -= (double)(ql - 1);        // undo B = A * e^t rescale
        g_loss[b] = (float)(-ll / (double)kl);

        __threadfence();
        unsigned prev = atomicAdd(&g_ctr, 1u);
        if (prev == BB - 1) {
            g_ctr = 0;
            __threadfence();
            float s = 0.f;
            for (int bb = 0; bb < BB; bb++) s += g_loss[bb];
            out[0] = s / (float)BB;
        }
    }
}

extern "C" void kernel_launch(void* const* d_in, const int* in_sizes, int n_in,
                              void* d_out, int out_size) {
    const float* attn     = (const float*)d_in[0];
    const int*   in_lens  = (const int*)d_in[1];
    const int*   out_lens = (const int*)d_in[2];

    zlog_kernel<<<dim3((TQQ + 7) / 8, BB), 256>>>(attn, in_lens, out_lens);
    dp_kernel<<<BB, 128>>>(attn, in_lens, out_lens, (float*)d_out);
}

// round 12
// speedup vs baseline: 9.4040x; 1.1315x over previous
#include <cuda_runtime.h>
#include <cstdint>

#define BB   32
#define TQQ  2000
#define TKK  512
#define EXNEG (-2000000)
#define PBLANK 0.36787944117144233f   /* e^-1 */
#define L2E 1.4426950408889634f
#define FULLW 0xffffffffu

__device__ float    g_loss[BB];
__device__ float    g_logz[BB * TQQ];
__device__ unsigned g_ctr = 0;

__device__ __forceinline__ float ex2f_(float x) {
    float r; asm("ex2.approx.ftz.f32 %0, %1;" : "=f"(r) : "f"(x)); return r;
}

// ---------------------------------------------------------------------------
// Kernel 1: per-row log partition  logZ = log(e^-1 + sum_{j<kl} exp(x)).
// Chunks fully beyond kl are skipped (warp-uniform) — halves DRAM traffic
// in expectation.
// ---------------------------------------------------------------------------
__global__ __launch_bounds__(256) void zlog_kernel(const float* __restrict__ attn,
                                                   const int* __restrict__ in_lens,
                                                   const int* __restrict__ out_lens) {
    int b    = blockIdx.y;
    int warp = threadIdx.x >> 5;
    int lane = threadIdx.x & 31;
    int t    = blockIdx.x * 8 + warp;
    if (t >= TQQ) return;
    int kl = min(max(in_lens[b], 1), TKK);
    int ql = min(max(out_lens[b], 1), TQQ);
    if (t >= ql) return;

    const float4* row = (const float4*)(attn + ((size_t)b * TQQ + t) * TKK);
    float s = 0.f;
#pragma unroll
    for (int k = 0; k < 4; k++) {
        if (128 * k < kl) {
            float4 v = __ldg(row + lane + 32 * k);
            int j = 4 * (lane + 32 * k);
            float a0 = (j + 0 < kl) ? __expf(v.x) : 0.f;
            float a1 = (j + 1 < kl) ? __expf(v.y) : 0.f;
            float a2 = (j + 2 < kl) ? __expf(v.z) : 0.f;
            float a3 = (j + 3 < kl) ? __expf(v.w) : 0.f;
            s += (a0 + a1) + (a2 + a3);
        }
    }
#pragma unroll
    for (int o = 16; o; o >>= 1) s += __shfl_xor_sync(FULLW, s, o);
    if (lane == 0) g_logz[b * TQQ + t] = __logf(PBLANK + s);
}

// ---------------------------------------------------------------------------
// Kernel 2: CTC forward recursion. B-domain, 4 steps per exchange/barrier
// (lockstep), per-thread block floating point, 8-row prefetch.
// 128 threads; thread i owns states 8i..8i+7. Warps whose states all lie
// beyond 2kl skip the group body (barrier only). Exchange via float4.
// ---------------------------------------------------------------------------
__global__ __launch_bounds__(128, 1) void dp_kernel(const float* __restrict__ attn,
                                                    const int* __restrict__ in_lens,
                                                    const int* __restrict__ out_lens,
                                                    float* __restrict__ out) {
    __shared__ float4 xch4[2][5][4];  // [parity][warp+1][quad]; row 0 = const
    __shared__ float sm_even[513];
    __shared__ float sm_odd[513];
    __shared__ int   sm_ex[513];
    __shared__ float red[128];

    int b    = blockIdx.x;
    int tid  = threadIdx.x;
    int lane = tid & 31;
    int warp = tid >> 5;
    int kl = min(max(in_lens[b], 1), TKK);
    int ql = min(max(out_lens[b], 1), TQQ);

    const float4* base4 = (const float4*)(attn + (size_t)b * TQQ * TKK) + tid;

    bool wact = (128 * warp) <= kl;       // warp has any state <= 2kl+1
    float bk0 = ((tid * 4 + 0) < kl) ? L2E : -1e30f;
    float bk1 = ((tid * 4 + 1) < kl) ? L2E : -1e30f;
    float bk2 = ((tid * 4 + 2) < kl) ? L2E : -1e30f;
    float bk3 = ((tid * 4 + 3) < kl) ? L2E : -1e30f;

    if (tid < 2) {
        xch4[tid][0][0] = make_float4(0.f, 0.f, 0.f, 0.f);
        xch4[tid][0][1] = make_float4(0.f, 0.f, 0.f, 0.f);
        xch4[tid][0][2] = make_float4(__int_as_float(EXNEG), 0.f, 0.f, 0.f);
        xch4[tid][0][3] = make_float4(0.f, 0.f, 0.f, 0.f);
    }

    // ---- row 0 init (B_0 = A_0) ----
    float4 x0 = __ldg(base4);
    float c8[8];
#pragma unroll
    for (int k = 0; k < 8; k++) c8[k] = 0.f;
    float a1024 = 0.f;
    int   exo   = EXNEG;
    if (tid == 0) { c8[0] = PBLANK; c8[1] = __expf(x0.x); exo = 0; }

    // ---- prefetch rows 1..8 ----
    int qm = ql - 1;
    float4 xs0 = __ldg(base4 + (size_t)min(1, qm) * 128);
    float4 xs1 = __ldg(base4 + (size_t)min(2, qm) * 128);
    float4 xs2 = __ldg(base4 + (size_t)min(3, qm) * 128);
    float4 xs3 = __ldg(base4 + (size_t)min(4, qm) * 128);
    float4 xs4 = __ldg(base4 + (size_t)min(5, qm) * 128);
    float4 xs5 = __ldg(base4 + (size_t)min(6, qm) * 128);
    float4 xs6 = __ldg(base4 + (size_t)min(7, qm) * 128);
    float4 xs7 = __ldg(base4 + (size_t)min(8, qm) * 128);

    int t = 1;

#define EMIT(XC, BK) ex2f_(fmaf((XC), L2E, (BK)))
#define PAIRS(DST, SRC, J, EM)                                                 \
    { float se_ = SRC[J] + SRC[J - 1]; DST[J] = se_;                           \
      DST[J + 1] = (SRC[J + 1] + se_) * (EM); }

#define GROUP(S0, S1, S2, S3, REFILL, GUARDED)                                 \
    {                                                                          \
        int p_ = ((t - 1) >> 2) & 1;                                           \
        float e00, e01, e02, e03, e10, e11, e12, e13;                          \
        float e20, e21, e22, e23, e30, e31, e32, e33;                          \
        if (wact) {                                                            \
            e00 = EMIT((S0).x, bk0); e01 = EMIT((S0).y, bk1);                  \
            e02 = EMIT((S0).z, bk2); e03 = EMIT((S0).w, bk3);                  \
            e10 = EMIT((S1).x, bk0); e11 = EMIT((S1).y, bk1);                  \
            e12 = EMIT((S1).z, bk2); e13 = EMIT((S1).w, bk3);                  \
            e20 = EMIT((S2).x, bk0); e21 = EMIT((S2).y, bk1);                  \
            e22 = EMIT((S2).z, bk2); e23 = EMIT((S2).w, bk3);                  \
            e30 = EMIT((S3).x, bk0); e31 = EMIT((S3).y, bk1);                  \
            e32 = EMIT((S3).z, bk2); e33 = EMIT((S3).w, bk3);                  \
            if (REFILL) {                                                      \
                (S0) = __ldg(base4 + (size_t)min(t + 8,  qm) * 128);           \
                (S1) = __ldg(base4 + (size_t)min(t + 9,  qm) * 128);           \
                (S2) = __ldg(base4 + (size_t)min(t + 10, qm) * 128);           \
                (S3) = __ldg(base4 + (size_t)min(t + 11, qm) * 128);           \
            }                                                                  \
            if (lane == 31) {                                                  \
                float4* wb = xch4[p_][warp + 1];                               \
                wb[0] = make_float4(c8[0], c8[1], c8[2], c8[3]);               \
                wb[1] = make_float4(c8[4], c8[5], c8[6], c8[7]);               \
                wb[2] = make_float4(__int_as_float(exo), e01, e02, e03);       \
                wb[3] = make_float4(e12, e13, e23, 0.f);                       \
            }                                                                  \
        }                                                                      \
        __syncthreads();                                                       \
        if (wact) {                                                            \
            float h_[8]; int he_;                                              \
            float f01, f02, f03, f12, f13, f23;                                \
            h_[0] = __shfl_up_sync(FULLW, c8[0], 1);                           \
            h_[1] = __shfl_up_sync(FULLW, c8[1], 1);                           \
            h_[2] = __shfl_up_sync(FULLW, c8[2], 1);                           \
            h_[3] = __shfl_up_sync(FULLW, c8[3], 1);                           \
            h_[4] = __shfl_up_sync(FULLW, c8[4], 1);                           \
            h_[5] = __shfl_up_sync(FULLW, c8[5], 1);                           \
            h_[6] = __shfl_up_sync(FULLW, c8[6], 1);                           \
            h_[7] = __shfl_up_sync(FULLW, c8[7], 1);                           \
            he_  = __shfl_up_sync(FULLW, exo, 1);                              \
            f01 = __shfl_up_sync(FULLW, e01, 1);                               \
            f02 = __shfl_up_sync(FULLW, e02, 1);                               \
            f03 = __shfl_up_sync(FULLW, e03, 1);                               \
            f12 = __shfl_up_sync(FULLW, e12, 1);                               \
            f13 = __shfl_up_sync(FULLW, e13, 1);                               \
            f23 = __shfl_up_sync(FULLW, e23, 1);                               \
            if (lane == 0) {                                                   \
                const float4* rb = xch4[p_][warp];                             \
                float4 q0 = rb[0], q1 = rb[1], q2 = rb[2], q3 = rb[3];         \
                h_[0] = q0.x; h_[1] = q0.y; h_[2] = q0.z; h_[3] = q0.w;        \
                h_[4] = q1.x; h_[5] = q1.y; h_[6] = q1.z; h_[7] = q1.w;        \
                he_ = __float_as_int(q2.x);                                    \
                f01 = q2.y; f02 = q2.z; f03 = q2.w;                            \
                f12 = q3.x; f13 = q3.y; f23 = q3.z;                            \
            }                                                                  \
            int bse = max(exo, he_);                                           \
            int d0_ = 127 + (he_ - bse); if (d0_ < 0) d0_ = 0;                 \
            int d1_ = 127 + (exo - bse); if (d1_ < 0) d1_ = 0;                 \
            float sh_ = __int_as_float(d0_ << 23);                             \
            float so_ = __int_as_float(d1_ << 23);                             \
            float A_[16], B_[16];                                              \
            A_[0] = h_[0] * sh_; A_[1] = h_[1] * sh_;                          \
            A_[2] = h_[2] * sh_; A_[3] = h_[3] * sh_;                          \
            A_[4] = h_[4] * sh_; A_[5] = h_[5] * sh_;                          \
            A_[6] = h_[6] * sh_; A_[7] = h_[7] * sh_;                          \
            A_[8]  = c8[0] * so_; A_[9]  = c8[1] * so_;                        \
            A_[10] = c8[2] * so_; A_[11] = c8[3] * so_;                        \
            A_[12] = c8[4] * so_; A_[13] = c8[5] * so_;                        \
            A_[14] = c8[6] * so_; A_[15] = c8[7] * so_;                        \
            float n4 = a1024 * so_;                                            \
            if (!(GUARDED) || (t + 0 < ql)) {                                  \
                PAIRS(B_, A_, 2, f01) PAIRS(B_, A_, 4, f02)                    \
                PAIRS(B_, A_, 6, f03)                                          \
                PAIRS(B_, A_, 8, e00) PAIRS(B_, A_, 10, e01)                   \
                PAIRS(B_, A_, 12, e02) PAIRS(B_, A_, 14, e03)                  \
                n4 = n4 + A_[15];                                              \
            } else {                                                           \
                _Pragma("unroll")                                              \
                for (int j_ = 2; j_ < 16; j_++) B_[j_] = A_[j_];               \
            }                                                                  \
            if (!(GUARDED) || (t + 1 < ql)) {                                  \
                PAIRS(A_, B_, 4, f12) PAIRS(A_, B_, 6, f13)                    \
                PAIRS(A_, B_, 8, e10) PAIRS(A_, B_, 10, e11)                   \
                PAIRS(A_, B_, 12, e12) PAIRS(A_, B_, 14, e13)                  \
                n4 = n4 + B_[15];                                              \
            } else {                                                           \
                _Pragma("unroll")                                              \
                for (int j_ = 4; j_ < 16; j_++) A_[j_] = B_[j_];               \
            }                                                                  \
            if (!(GUARDED) || (t + 2 < ql)) {                                  \
                PAIRS(B_, A_, 6, f23)                                          \
                PAIRS(B_, A_, 8, e20) PAIRS(B_, A_, 10, e21)                   \
                PAIRS(B_, A_, 12, e22) PAIRS(B_, A_, 14, e23)                  \
                n4 = n4 + A_[15];                                              \
            } else {                                                           \
                _Pragma("unroll")                                              \
                for (int j_ = 6; j_ < 16; j_++) B_[j_] = A_[j_];               \
            }                                                                  \
            if (!(GUARDED) || (t + 3 < ql)) {                                  \
                PAIRS(A_, B_, 8, e30) PAIRS(A_, B_, 10, e31)                   \
                PAIRS(A_, B_, 12, e32) PAIRS(A_, B_, 14, e33)                  \
                n4 = n4 + B_[15];                                              \
            } else {                                                           \
                _Pragma("unroll")                                              \
                for (int j_ = 8; j_ < 16; j_++) A_[j_] = B_[j_];               \
            }                                                                  \
            float m_ = fmaxf(fmaxf(fmaxf(A_[8], A_[9]), fmaxf(A_[10], A_[11])),\
                             fmaxf(fmaxf(A_[12], A_[13]),                      \
                                   fmaxf(A_[14], A_[15])));                    \
            m_ = fmaxf(m_, n4);                                                \
            int kk_ = ((__float_as_int(m_) >> 23) & 255) - 127;                \
            float sc_ = __int_as_float((127 - kk_) << 23);                     \
            c8[0] = A_[8]  * sc_; c8[1] = A_[9]  * sc_;                        \
            c8[2] = A_[10] * sc_; c8[3] = A_[11] * sc_;                        \
            c8[4] = A_[12] * sc_; c8[5] = A_[13] * sc_;                        \
            c8[6] = A_[14] * sc_; c8[7] = A_[15] * sc_;                        \
            a1024 = n4 * sc_;                                                  \
            exo = (m_ > 0.f) ? (bse + kk_) : EXNEG;                            \
        }                                                                      \
        t += 4;                                                                \
    }

    while (t + 7 < ql) {
        GROUP(xs0, xs1, xs2, xs3, 1, 0)
        GROUP(xs4, xs5, xs6, xs7, 1, 0)
    }
    if (t + 3 < ql) {
        GROUP(xs0, xs1, xs2, xs3, 0, 0)
        if (t < ql) { GROUP(xs4, xs5, xs6, xs7, 0, 1) }
    } else if (t < ql) {
        GROUP(xs0, xs1, xs2, xs3, 0, 1)
    }

    // ---- epilogue ----
#pragma unroll
    for (int k = 0; k < 4; k++) {
        sm_even[tid * 4 + k] = c8[2 * k];
        sm_odd [tid * 4 + k] = c8[2 * k + 1];
        sm_ex  [tid * 4 + k] = exo;
    }
    if (tid == 127) { sm_even[512] = a1024; sm_odd[512] = 0.f; sm_ex[512] = exo; }

    float lz = 0.f;
    for (int tt = tid; tt < ql; tt += 128) lz += g_logz[b * TQQ + tt];
    red[tid] = lz;
    __syncthreads();
#pragma unroll
    for (int s = 64; s; s >>= 1) {
        if (tid < s) red[tid] += red[tid + s];
        __syncthreads();
    }

    if (tid == 0) {
        float mE = sm_even[kl];     int eE = sm_ex[kl];       // state 2kl
        float mL = sm_odd[kl - 1];  int eL = sm_ex[kl - 1];   // state 2kl-1
        double ll;
        if (mE == 0.f && mL == 0.f) {
            ll = -1e9;
        } else {
            int eM = max(mE > 0.f ? eE : EXNEG, mL > 0.f ? eL : EXNEG);
            double s2 = 0.0;
            if (mE > 0.f) s2 += (double)mE * exp2((double)(eE - eM));
            if (mL > 0.f) s2 += (double)mL * exp2((double)(eL - eM));
            ll = log(s2) + (double)eM * 0.6931471805599453;
        }
        ll -= (double)red[0];          // - sum_t log Z_t
        ll -= (double)(ql - 1);        // undo B = A * e^t rescale
        g_loss[b] = (float)(-ll / (double)kl);

        __threadfence();
        unsigned prev = atomicAdd(&g_ctr, 1u);
        if (prev == BB - 1) {
            g_ctr = 0;
            __threadfence();
            float s = 0.f;
            for (int bb = 0; bb < BB; bb++) s += g_loss[bb];
            out[0] = s / (float)BB;
        }
    }
}

extern "C" void kernel_launch(void* const* d_in, const int* in_sizes, int n_in,
                              void* d_out, int out_size) {
    const float* attn     = (const float*)d_in[0];
    const int*   in_lens  = (const int*)d_in[1];
    const int*   out_lens = (const int*)d_in[2];

    zlog_kernel<<<dim3((TQQ + 7) / 8, BB), 256>>>(attn, in_lens, out_lens);
    dp_kernel<<<BB, 128>>>(attn, in_lens, out_lens, (float*)d_out);
}

// round 13
// speedup vs baseline: 10.6096x; 1.1282x over previous
#include <cuda_runtime.h>
#include <cstdint>

#define BB   32
#define TQQ  2000
#define TKK  512
#define EXNEG (-2000000)
#define PBLANK 0.36787944117144233f   /* e^-1 */
#define L2E 1.4426950408889634f
#define FULLW 0xffffffffu
#define RSTRIDE 20                    /* record slot stride in floats (80B) */

__device__ float    g_loss[BB];
__device__ float    g_logz[BB * TQQ];
__device__ unsigned g_ctr = 0;

__device__ __forceinline__ float ex2f_(float x) {
    float r; asm("ex2.approx.ftz.f32 %0, %1;" : "=f"(r) : "f"(x)); return r;
}

// ---------------------------------------------------------------------------
// Kernel 1: per-row log partition  logZ = log(e^-1 + sum_{j<kl} exp(x)).
// Chunks fully beyond kl are skipped (warp-uniform).
// ---------------------------------------------------------------------------
__global__ __launch_bounds__(256) void zlog_kernel(const float* __restrict__ attn,
                                                   const int* __restrict__ in_lens,
                                                   const int* __restrict__ out_lens) {
    int b    = blockIdx.y;
    int warp = threadIdx.x >> 5;
    int lane = threadIdx.x & 31;
    int t    = blockIdx.x * 8 + warp;
    if (t >= TQQ) return;
    int kl = min(max(in_lens[b], 1), TKK);
    int ql = min(max(out_lens[b], 1), TQQ);
    if (t >= ql) return;

    const float4* row = (const float4*)(attn + ((size_t)b * TQQ + t) * TKK);
    float s = 0.f;
#pragma unroll
    for (int k = 0; k < 4; k++) {
        if (128 * k < kl) {
            float4 v = __ldg(row + lane + 32 * k);
            int j = 4 * (lane + 32 * k);
            float a0 = (j + 0 < kl) ? __expf(v.x) : 0.f;
            float a1 = (j + 1 < kl) ? __expf(v.y) : 0.f;
            float a2 = (j + 2 < kl) ? __expf(v.z) : 0.f;
            float a3 = (j + 3 < kl) ? __expf(v.w) : 0.f;
            s += (a0 + a1) + (a2 + a3);
        }
    }
#pragma unroll
    for (int o = 16; o; o >>= 1) s += __shfl_xor_sync(FULLW, s, o);
    if (lane == 0) g_logz[b * TQQ + t] = __logf(PBLANK + s);
}

// ---------------------------------------------------------------------------
// Kernel 2: CTC forward recursion. B-domain, 4 steps per exchange/barrier,
// per-thread block floating point, 8-row prefetch with pointer-increment
// refill, halo exchange via uniform smem records (no shfls, no divergent
// lanes). 128 threads; thread i owns states 8i..8i+7.
// ---------------------------------------------------------------------------
__global__ __launch_bounds__(128, 1) void dp_kernel(const float* __restrict__ attn,
                                                    const int* __restrict__ in_lens,
                                                    const int* __restrict__ out_lens,
                                                    float* __restrict__ out) {
    // record: [parity][slot 0..128][RSTRIDE floats]; slot 0 = constant left edge
    __shared__ float rec[2][129 * RSTRIDE];
    __shared__ float sm_even[513];
    __shared__ float sm_odd[513];
    __shared__ int   sm_ex[513];
    __shared__ float red[128];

    int b    = blockIdx.x;
    int tid  = threadIdx.x;
    int warp = tid >> 5;
    int kl = min(max(in_lens[b], 1), TKK);
    int ql = min(max(out_lens[b], 1), TQQ);

    const float4* base4 = (const float4*)(attn + (size_t)b * TQQ * TKK) + tid;

    bool wact = (128 * warp) <= kl;       // warp has any state <= 2kl+1
    float bk0 = ((tid * 4 + 0) < kl) ? L2E : -1e30f;
    float bk1 = ((tid * 4 + 1) < kl) ? L2E : -1e30f;
    float bk2 = ((tid * 4 + 2) < kl) ? L2E : -1e30f;
    float bk3 = ((tid * 4 + 3) < kl) ? L2E : -1e30f;

    if (tid < 2) {
        float4* z = (float4*)&rec[tid][0];
        z[0] = make_float4(0.f, 0.f, 0.f, 0.f);
        z[1] = make_float4(0.f, 0.f, 0.f, 0.f);
        z[2] = make_float4(__int_as_float(EXNEG), 0.f, 0.f, 0.f);
        z[3] = make_float4(0.f, 0.f, 0.f, 0.f);
    }

    // ---- row 0 init (B_0 = A_0) ----
    float4 x0 = __ldg(base4);
    float c8[8];
#pragma unroll
    for (int k = 0; k < 8; k++) c8[k] = 0.f;
    float a1024 = 0.f;
    int   exo   = EXNEG;
    if (tid == 0) { c8[0] = PBLANK; c8[1] = __expf(x0.x); exo = 0; }

    // ---- prefetch rows 1..8 ----
    int qm = ql - 1;
    float4 xs0 = __ldg(base4 + (size_t)min(1, qm) * 128);
    float4 xs1 = __ldg(base4 + (size_t)min(2, qm) * 128);
    float4 xs2 = __ldg(base4 + (size_t)min(3, qm) * 128);
    float4 xs3 = __ldg(base4 + (size_t)min(4, qm) * 128);
    float4 xs4 = __ldg(base4 + (size_t)min(5, qm) * 128);
    float4 xs5 = __ldg(base4 + (size_t)min(6, qm) * 128);
    float4 xs6 = __ldg(base4 + (size_t)min(7, qm) * 128);
    float4 xs7 = __ldg(base4 + (size_t)min(8, qm) * 128);

    const float4* rp = base4 + (size_t)9 * 128;   // next unfetched row (t=1 steady)
    int t = 1;

#define EMIT(XC, BK) ex2f_(fmaf((XC), L2E, (BK)))
#define PAIRS(DST, SRC, J, EM)                                                 \
    { float se_ = SRC[J] + SRC[J - 1]; DST[J] = se_;                           \
      DST[J + 1] = (SRC[J + 1] + se_) * (EM); }

#define GROUP(S0, S1, S2, S3, REFILL, GUARDED)                                 \
    {                                                                          \
        int p_ = ((t - 1) >> 2) & 1;                                           \
        float e00, e01, e02, e03, e10, e11, e12, e13;                          \
        float e20, e21, e22, e23, e30, e31, e32, e33;                          \
        if (wact) {                                                            \
            e00 = EMIT((S0).x, bk0); e01 = EMIT((S0).y, bk1);                  \
            e02 = EMIT((S0).z, bk2); e03 = EMIT((S0).w, bk3);                  \
            e10 = EMIT((S1).x, bk0); e11 = EMIT((S1).y, bk1);                  \
            e12 = EMIT((S1).z, bk2); e13 = EMIT((S1).w, bk3);                  \
            e20 = EMIT((S2).x, bk0); e21 = EMIT((S2).y, bk1);                  \
            e22 = EMIT((S2).z, bk2); e23 = EMIT((S2).w, bk3);                  \
            e30 = EMIT((S3).x, bk0); e31 = EMIT((S3).y, bk1);                  \
            e32 = EMIT((S3).z, bk2); e33 = EMIT((S3).w, bk3);                  \
            if ((REFILL) == 1) {                                               \
                (S0) = __ldg(rp);                                              \
                (S1) = __ldg(rp + 128);                                        \
                (S2) = __ldg(rp + 256);                                        \
                (S3) = __ldg(rp + 384);                                        \
                rp += 512;                                                     \
            } else if ((REFILL) == 2) {                                        \
                (S0) = __ldg(base4 + (size_t)min(t + 8,  qm) * 128);           \
                (S1) = __ldg(base4 + (size_t)min(t + 9,  qm) * 128);           \
                (S2) = __ldg(base4 + (size_t)min(t + 10, qm) * 128);           \
                (S3) = __ldg(base4 + (size_t)min(t + 11, qm) * 128);           \
            }                                                                  \
            float4* wb = (float4*)&rec[p_][(tid + 1) * RSTRIDE];               \
            wb[0] = make_float4(c8[0], c8[1], c8[2], c8[3]);                   \
            wb[1] = make_float4(c8[4], c8[5], c8[6], c8[7]);                   \
            wb[2] = make_float4(__int_as_float(exo), e01, e02, e03);           \
            wb[3] = make_float4(e12, e13, e23, 0.f);                           \
        }                                                                      \
        __syncthreads();                                                       \
        if (wact) {                                                            \
            const float4* rb = (const float4*)&rec[p_][tid * RSTRIDE];         \
            float4 q0 = rb[0], q1 = rb[1], q2 = rb[2], q3 = rb[3];             \
            float h_[8]; int he_;                                              \
            h_[0] = q0.x; h_[1] = q0.y; h_[2] = q0.z; h_[3] = q0.w;            \
            h_[4] = q1.x; h_[5] = q1.y; h_[6] = q1.z; h_[7] = q1.w;            \
            he_ = __float_as_int(q2.x);                                        \
            float f01 = q2.y, f02 = q2.z, f03 = q2.w;                          \
            float f12 = q3.x, f13 = q3.y, f23 = q3.z;                          \
            int bse = max(exo, he_);                                           \
            int d0_ = 127 + (he_ - bse); if (d0_ < 0) d0_ = 0;                 \
            int d1_ = 127 + (exo - bse); if (d1_ < 0) d1_ = 0;                 \
            float sh_ = __int_as_float(d0_ << 23);                             \
            float so_ = __int_as_float(d1_ << 23);                             \
            float A_[16], B_[16];                                              \
            A_[0] = h_[0] * sh_; A_[1] = h_[1] * sh_;                          \
            A_[2] = h_[2] * sh_; A_[3] = h_[3] * sh_;                          \
            A_[4] = h_[4] * sh_; A_[5] = h_[5] * sh_;                          \
            A_[6] = h_[6] * sh_; A_[7] = h_[7] * sh_;                          \
            A_[8]  = c8[0] * so_; A_[9]  = c8[1] * so_;                        \
            A_[10] = c8[2] * so_; A_[11] = c8[3] * so_;                        \
            A_[12] = c8[4] * so_; A_[13] = c8[5] * so_;                        \
            A_[14] = c8[6] * so_; A_[15] = c8[7] * so_;                        \
            float n4 = a1024 * so_;                                            \
            if (!(GUARDED) || (t + 0 < ql)) {                                  \
                PAIRS(B_, A_, 2, f01) PAIRS(B_, A_, 4, f02)                    \
                PAIRS(B_, A_, 6, f03)                                          \
                PAIRS(B_, A_, 8, e00) PAIRS(B_, A_, 10, e01)                   \
                PAIRS(B_, A_, 12, e02) PAIRS(B_, A_, 14, e03)                  \
                n4 = n4 + A_[15];                                              \
            } else {                                                           \
                _Pragma("unroll")                                              \
                for (int j_ = 2; j_ < 16; j_++) B_[j_] = A_[j_];               \
            }                                                                  \
            if (!(GUARDED) || (t + 1 < ql)) {                                  \
                PAIRS(A_, B_, 4, f12) PAIRS(A_, B_, 6, f13)                    \
                PAIRS(A_, B_, 8, e10) PAIRS(A_, B_, 10, e11)                   \
                PAIRS(A_, B_, 12, e12) PAIRS(A_, B_, 14, e13)                  \
                n4 = n4 + B_[15];                                              \
            } else {                                                           \
                _Pragma("unroll")                                              \
                for (int j_ = 4; j_ < 16; j_++) A_[j_] = B_[j_];               \
            }                                                                  \
            if (!(GUARDED) || (t + 2 < ql)) {                                  \
                PAIRS(B_, A_, 6, f23)                                          \
                PAIRS(B_, A_, 8, e20) PAIRS(B_, A_, 10, e21)                   \
                PAIRS(B_, A_, 12, e22) PAIRS(B_, A_, 14, e23)                  \
                n4 = n4 + A_[15];                                              \
            } else {                                                           \
                _Pragma("unroll")                                              \
                for (int j_ = 6; j_ < 16; j_++) B_[j_] = A_[j_];               \
            }                                                                  \
            if (!(GUARDED) || (t + 3 < ql)) {                                  \
                PAIRS(A_, B_, 8, e30) PAIRS(A_, B_, 10, e31)                   \
                PAIRS(A_, B_, 12, e32) PAIRS(A_, B_, 14, e33)                  \
                n4 = n4 + B_[15];                                              \
            } else {                                                           \
                _Pragma("unroll")                                              \
                for (int j_ = 8; j_ < 16; j_++) A_[j_] = B_[j_];               \
            }                                                                  \
            float m_ = fmaxf(fmaxf(fmaxf(A_[8], A_[9]), fmaxf(A_[10], A_[11])),\
                             fmaxf(fmaxf(A_[12], A_[13]),                      \
                                   fmaxf(A_[14], A_[15])));                    \
            m_ = fmaxf(m_, n4);                                                \
            int kk_ = ((__float_as_int(m_) >> 23) & 255) - 127;                \
            float sc_ = __int_as_float((127 - kk_) << 23);                     \
            c8[0] = A_[8]  * sc_; c8[1] = A_[9]  * sc_;                        \
            c8[2] = A_[10] * sc_; c8[3] = A_[11] * sc_;                        \
            c8[4] = A_[12] * sc_; c8[5] = A_[13] * sc_;                        \
            c8[6] = A_[14] * sc_; c8[7] = A_[15] * sc_;                        \
            a1024 = n4 * sc_;                                                  \
            exo = (m_ > 0.f) ? (bse + kk_) : EXNEG;                            \
        }                                                                      \
        t += 4;                                                                \
    }

    // steady state: unclamped pointer refill (rows t+8..t+11 always valid)
    while (t + 15 < ql) {
        GROUP(xs0, xs1, xs2, xs3, 1, 0)
        GROUP(xs4, xs5, xs6, xs7, 1, 0)
    }
    // near-tail: clamped refill (runs at most once)
    while (t + 7 < ql) {
        GROUP(xs0, xs1, xs2, xs3, 2, 0)
        GROUP(xs4, xs5, xs6, xs7, 2, 0)
    }
    if (t + 3 < ql) {
        GROUP(xs0, xs1, xs2, xs3, 0, 0)
        if (t < ql) { GROUP(xs4, xs5, xs6, xs7, 0, 1) }
    } else if (t < ql) {
        GROUP(xs0, xs1, xs2, xs3, 0, 1)
    }

    // ---- epilogue ----
#pragma unroll
    for (int k = 0; k < 4; k++) {
        sm_even[tid * 4 + k] = c8[2 * k];
        sm_odd [tid * 4 + k] = c8[2 * k + 1];
        sm_ex  [tid * 4 + k] = exo;
    }
    if (tid == 127) { sm_even[512] = a1024; sm_odd[512] = 0.f; sm_ex[512] = exo; }

    float lz = 0.f;
    for (int tt = tid; tt < ql; tt += 128) lz += g_logz[b * TQQ + tt];
    red[tid] = lz;
    __syncthreads();
#pragma unroll
    for (int s = 64; s; s >>= 1) {
        if (tid < s) red[tid] += red[tid + s];
        __syncthreads();
    }

    if (tid == 0) {
        float mE = sm_even[kl];     int eE = sm_ex[kl];       // state 2kl
        float mL = sm_odd[kl - 1];  int eL = sm_ex[kl - 1];   // state 2kl-1
        double ll;
        if (mE == 0.f && mL == 0.f) {
            ll = -1e9;
        } else {
            int eM = max(mE > 0.f ? eE : EXNEG, mL > 0.f ? eL : EXNEG);
            double s2 = 0.0;
            if (mE > 0.f) s2 += (double)mE * exp2((double)(eE - eM));
            if (mL > 0.f) s2 += (double)mL * exp2((double)(eL - eM));
            ll = log(s2) + (double)eM * 0.6931471805599453;
        }
        ll -= (double)red[0];          // - sum_t log Z_t
        ll -= (double)(ql - 1);        // undo B = A * e^t rescale
        g_loss[b] = (float)(-ll / (double)kl);

        __threadfence();
        unsigned prev = atomicAdd(&g_ctr, 1u);
        if (prev == BB - 1) {
            g_ctr = 0;
            __threadfence();
            float s = 0.f;
            for (int bb = 0; bb < BB; bb++) s += g_loss[bb];
            out[0] = s / (float)BB;
        }
    }
}

extern "C" void kernel_launch(void* const* d_in, const int* in_sizes, int n_in,
                              void* d_out, int out_size) {
    const float* attn     = (const float*)d_in[0];
    const int*   in_lens  = (const int*)d_in[1];
    const int*   out_lens = (const int*)d_in[2];

    zlog_kernel<<<dim3((TQQ + 7) / 8, BB), 256>>>(attn, in_lens, out_lens);
    dp_kernel<<<BB, 128>>>(attn, in_lens, out_lens, (float*)d_out);
}

// round 14
// speedup vs baseline: 10.6711x; 1.0058x over previous
#include <cuda_runtime.h>
#include <cstdint>

#define BB   32
#define TQQ  2000
#define TKK  512
#define EXNEG (-2000000)
#define PBLANK 0.36787944117144233f   /* e^-1 */
#define L2E 1.4426950408889634f
#define FULLW 0xffffffffu
#define RSTRIDE 20                    /* record slot stride in floats (80B) */

__device__ float    g_loss[BB];
__device__ float    g_logz[BB * TQQ];
__device__ unsigned g_ctr = 0;

__device__ __forceinline__ float ex2f_(float x) {
    float r; asm("ex2.approx.ftz.f32 %0, %1;" : "=f"(r) : "f"(x)); return r;
}

// ---------------------------------------------------------------------------
// Kernel 1: per-row log partition  logZ = log(e^-1 + sum_{j<kl} exp(x)).
// Chunks fully beyond kl are skipped (warp-uniform).
// ---------------------------------------------------------------------------
__global__ __launch_bounds__(256) void zlog_kernel(const float* __restrict__ attn,
                                                   const int* __restrict__ in_lens,
                                                   const int* __restrict__ out_lens) {
    int b    = blockIdx.y;
    int warp = threadIdx.x >> 5;
    int lane = threadIdx.x & 31;
    int t    = blockIdx.x * 8 + warp;
    if (t >= TQQ) return;
    int kl = min(max(in_lens[b], 1), TKK);
    int ql = min(max(out_lens[b], 1), TQQ);
    if (t >= ql) return;

    const float4* row = (const float4*)(attn + ((size_t)b * TQQ + t) * TKK);
    float s = 0.f;
#pragma unroll
    for (int k = 0; k < 4; k++) {
        if (128 * k < kl) {
            float4 v = __ldg(row + lane + 32 * k);
            int j = 4 * (lane + 32 * k);
            float a0 = (j + 0 < kl) ? __expf(v.x) : 0.f;
            float a1 = (j + 1 < kl) ? __expf(v.y) : 0.f;
            float a2 = (j + 2 < kl) ? __expf(v.z) : 0.f;
            float a3 = (j + 3 < kl) ? __expf(v.w) : 0.f;
            s += (a0 + a1) + (a2 + a3);
        }
    }
#pragma unroll
    for (int o = 16; o; o >>= 1) s += __shfl_xor_sync(FULLW, s, o);
    if (lane == 0) g_logz[b * TQQ + t] = __logf(PBLANK + s);
}

// ---------------------------------------------------------------------------
// Kernel 2: CTC forward recursion. B-domain, 4 steps per exchange/barrier,
// LAZY per-thread block floating point (mantissas unnormalized; claimed
// exponent exo + pending bias kk; alignment multiply folds both), 8-row
// prefetch with pointer refill, smem-record halo exchange.
// Invariant: true_state = c8[j] * 2^(exo - kk).
// ---------------------------------------------------------------------------
__global__ __launch_bounds__(128, 1) void dp_kernel(const float* __restrict__ attn,
                                                    const int* __restrict__ in_lens,
                                                    const int* __restrict__ out_lens,
                                                    float* __restrict__ out) {
    __shared__ float rec[2][129 * RSTRIDE];
    __shared__ float sm_even[513];
    __shared__ float sm_odd[513];
    __shared__ int   sm_ex[513];
    __shared__ float red[128];

    int b    = blockIdx.x;
    int tid  = threadIdx.x;
    int warp = tid >> 5;
    int kl = min(max(in_lens[b], 1), TKK);
    int ql = min(max(out_lens[b], 1), TQQ);

    const float4* base4 = (const float4*)(attn + (size_t)b * TQQ * TKK) + tid;

    bool wact = (128 * warp) <= kl;
    float bk0 = ((tid * 4 + 0) < kl) ? L2E : -1e30f;
    float bk1 = ((tid * 4 + 1) < kl) ? L2E : -1e30f;
    float bk2 = ((tid * 4 + 2) < kl) ? L2E : -1e30f;
    float bk3 = ((tid * 4 + 3) < kl) ? L2E : -1e30f;

    if (tid < 2) {
        float4* z = (float4*)&rec[tid][0];
        z[0] = make_float4(0.f, 0.f, 0.f, 0.f);
        z[1] = make_float4(0.f, 0.f, 0.f, 0.f);
        z[2] = make_float4(__int_as_float(EXNEG), 0.f, 0.f, 0.f);
        z[3] = make_float4(0.f, 0.f, 0.f, 0.f);     // kk = 0
    }

    // ---- row 0 init (B_0 = A_0) ----
    float4 x0 = __ldg(base4);
    float c8[8];
#pragma unroll
    for (int k = 0; k < 8; k++) c8[k] = 0.f;
    float a1024 = 0.f;
    int   exo   = EXNEG;
    int   kk    = 0;
    if (tid == 0) { c8[0] = PBLANK; c8[1] = __expf(x0.x); exo = 0; }

    // ---- prefetch rows 1..8 ----
    int qm = ql - 1;
    float4 xs0 = __ldg(base4 + (size_t)min(1, qm) * 128);
    float4 xs1 = __ldg(base4 + (size_t)min(2, qm) * 128);
    float4 xs2 = __ldg(base4 + (size_t)min(3, qm) * 128);
    float4 xs3 = __ldg(base4 + (size_t)min(4, qm) * 128);
    float4 xs4 = __ldg(base4 + (size_t)min(5, qm) * 128);
    float4 xs5 = __ldg(base4 + (size_t)min(6, qm) * 128);
    float4 xs6 = __ldg(base4 + (size_t)min(7, qm) * 128);
    float4 xs7 = __ldg(base4 + (size_t)min(8, qm) * 128);

    const float4* rp = base4 + (size_t)9 * 128;
    int t = 1;

#define EMIT(XC, BK) ex2f_(fmaf((XC), L2E, (BK)))
#define PAIRS(DST, SRC, J, EM)                                                 \
    { float se_ = SRC[J] + SRC[J - 1]; DST[J] = se_;                           \
      DST[J + 1] = (SRC[J + 1] + se_) * (EM); }

#define GROUP(S0, S1, S2, S3, REFILL, GUARDED)                                 \
    {                                                                          \
        int p_ = ((t - 1) >> 2) & 1;                                           \
        float e00, e01, e02, e03, e10, e11, e12, e13;                          \
        float e20, e21, e22, e23, e30, e31, e32, e33;                          \
        if (wact) {                                                            \
            e00 = EMIT((S0).x, bk0); e01 = EMIT((S0).y, bk1);                  \
            e02 = EMIT((S0).z, bk2); e03 = EMIT((S0).w, bk3);                  \
            e10 = EMIT((S1).x, bk0); e11 = EMIT((S1).y, bk1);                  \
            e12 = EMIT((S1).z, bk2); e13 = EMIT((S1).w, bk3);                  \
            e20 = EMIT((S2).x, bk0); e21 = EMIT((S2).y, bk1);                  \
            e22 = EMIT((S2).z, bk2); e23 = EMIT((S2).w, bk3);                  \
            e30 = EMIT((S3).x, bk0); e31 = EMIT((S3).y, bk1);                  \
            e32 = EMIT((S3).z, bk2); e33 = EMIT((S3).w, bk3);                  \
            if ((REFILL) == 1) {                                               \
                (S0) = __ldg(rp);                                              \
                (S1) = __ldg(rp + 128);                                        \
                (S2) = __ldg(rp + 256);                                        \
                (S3) = __ldg(rp + 384);                                        \
                rp += 512;                                                     \
            } else if ((REFILL) == 2) {                                        \
                (S0) = __ldg(base4 + (size_t)min(t + 8,  qm) * 128);           \
                (S1) = __ldg(base4 + (size_t)min(t + 9,  qm) * 128);           \
                (S2) = __ldg(base4 + (size_t)min(t + 10, qm) * 128);           \
                (S3) = __ldg(base4 + (size_t)min(t + 11, qm) * 128);           \
            }                                                                  \
            float4* wb = (float4*)&rec[p_][(tid + 1) * RSTRIDE];               \
            wb[0] = make_float4(c8[0], c8[1], c8[2], c8[3]);                   \
            wb[1] = make_float4(c8[4], c8[5], c8[6], c8[7]);                   \
            wb[2] = make_float4(__int_as_float(exo), e01, e02, e03);           \
            wb[3] = make_float4(e12, e13, e23, __int_as_float(kk));            \
        }                                                                      \
        __syncthreads();                                                       \
        if (wact) {                                                            \
            const float4* rb = (const float4*)&rec[p_][tid * RSTRIDE];         \
            float4 q0 = rb[0], q1 = rb[1], q2 = rb[2], q3 = rb[3];             \
            float h_[8]; int he_, kkL_;                                        \
            h_[0] = q0.x; h_[1] = q0.y; h_[2] = q0.z; h_[3] = q0.w;            \
            h_[4] = q1.x; h_[5] = q1.y; h_[6] = q1.z; h_[7] = q1.w;            \
            he_  = __float_as_int(q2.x);                                       \
            kkL_ = __float_as_int(q3.w);                                       \
            float f01 = q2.y, f02 = q2.z, f03 = q2.w;                          \
            float f12 = q3.x, f13 = q3.y, f23 = q3.z;                          \
            int bse = max(exo, he_);                                           \
            int d0_ = 127 + (he_ - kkL_) - bse; if (d0_ < 0) d0_ = 0;          \
            int d1_ = 127 + (exo - kk)   - bse; if (d1_ < 0) d1_ = 0;          \
            float sh_ = __int_as_float(d0_ << 23);                             \
            float so_ = __int_as_float(d1_ << 23);                             \
            float A_[16], B_[16];                                              \
            A_[0] = h_[0] * sh_; A_[1] = h_[1] * sh_;                          \
            A_[2] = h_[2] * sh_; A_[3] = h_[3] * sh_;                          \
            A_[4] = h_[4] * sh_; A_[5] = h_[5] * sh_;                          \
            A_[6] = h_[6] * sh_; A_[7] = h_[7] * sh_;                          \
            A_[8]  = c8[0] * so_; A_[9]  = c8[1] * so_;                        \
            A_[10] = c8[2] * so_; A_[11] = c8[3] * so_;                        \
            A_[12] = c8[4] * so_; A_[13] = c8[5] * so_;                        \
            A_[14] = c8[6] * so_; A_[15] = c8[7] * so_;                        \
            float n4 = a1024 * so_;                                            \
            if (!(GUARDED) || (t + 0 < ql)) {                                  \
                PAIRS(B_, A_, 2, f01) PAIRS(B_, A_, 4, f02)                    \
                PAIRS(B_, A_, 6, f03)                                          \
                PAIRS(B_, A_, 8, e00) PAIRS(B_, A_, 10, e01)                   \
                PAIRS(B_, A_, 12, e02) PAIRS(B_, A_, 14, e03)                  \
                n4 = n4 + A_[15];                                              \
            } else {                                                           \
                _Pragma("unroll")                                              \
                for (int j_ = 2; j_ < 16; j_++) B_[j_] = A_[j_];               \
            }                                                                  \
            if (!(GUARDED) || (t + 1 < ql)) {                                  \
                PAIRS(A_, B_, 4, f12) PAIRS(A_, B_, 6, f13)                    \
                PAIRS(A_, B_, 8, e10) PAIRS(A_, B_, 10, e11)                   \
                PAIRS(A_, B_, 12, e12) PAIRS(A_, B_, 14, e13)                  \
                n4 = n4 + B_[15];                                              \
            } else {                                                           \
                _Pragma("unroll")                                              \
                for (int j_ = 4; j_ < 16; j_++) A_[j_] = B_[j_];               \
            }                                                                  \
            if (!(GUARDED) || (t + 2 < ql)) {                                  \
                PAIRS(B_, A_, 6, f23)                                          \
                PAIRS(B_, A_, 8, e20) PAIRS(B_, A_, 10, e21)                   \
                PAIRS(B_, A_, 12, e22) PAIRS(B_, A_, 14, e23)                  \
                n4 = n4 + A_[15];                                              \
            } else {                                                           \
                _Pragma("unroll")                                              \
                for (int j_ = 6; j_ < 16; j_++) B_[j_] = A_[j_];               \
            }                                                                  \
            if (!(GUARDED) || (t + 3 < ql)) {                                  \
                PAIRS(A_, B_, 8, e30) PAIRS(A_, B_, 10, e31)                   \
                PAIRS(A_, B_, 12, e32) PAIRS(A_, B_, 14, e33)                  \
                n4 = n4 + B_[15];                                              \
            } else {                                                           \
                _Pragma("unroll")                                              \
                for (int j_ = 8; j_ < 16; j_++) A_[j_] = B_[j_];               \
            }                                                                  \
            /* lazy renorm: adopt mantissas unscaled, claim exponent */        \
            float m_ = fmaxf(fmaxf(fmaxf(A_[8], A_[9]), fmaxf(A_[10], A_[11])),\
                             fmaxf(fmaxf(A_[12], A_[13]),                      \
                                   fmaxf(A_[14], A_[15])));                    \
            m_ = fmaxf(m_, n4);                                                \
            c8[0] = A_[8];  c8[1] = A_[9];                                     \
            c8[2] = A_[10]; c8[3] = A_[11];                                    \
            c8[4] = A_[12]; c8[5] = A_[13];                                    \
            c8[6] = A_[14]; c8[7] = A_[15];                                    \
            a1024 = n4;                                                        \
            kk  = ((__float_as_int(m_) >> 23) & 255) - 127;                    \
            exo = bse + kk;                                                    \
        }                                                                      \
        t += 4;                                                                \
    }

    while (t + 15 < ql) {
        GROUP(xs0, xs1, xs2, xs3, 1, 0)
        GROUP(xs4, xs5, xs6, xs7, 1, 0)
    }
    while (t + 7 < ql) {
        GROUP(xs0, xs1, xs2, xs3, 2, 0)
        GROUP(xs4, xs5, xs6, xs7, 2, 0)
    }
    if (t + 3 < ql) {
        GROUP(xs0, xs1, xs2, xs3, 0, 0)
        if (t < ql) { GROUP(xs4, xs5, xs6, xs7, 0, 1) }
    } else if (t < ql) {
        GROUP(xs0, xs1, xs2, xs3, 0, 1)
    }

    // ---- epilogue: true exponent of stored mantissas is exo - kk ----
#pragma unroll
    for (int k = 0; k < 4; k++) {
        sm_even[tid * 4 + k] = c8[2 * k];
        sm_odd [tid * 4 + k] = c8[2 * k + 1];
        sm_ex  [tid * 4 + k] = exo - kk;
    }
    if (tid == 127) { sm_even[512] = a1024; sm_odd[512] = 0.f; sm_ex[512] = exo - kk; }

    float lz = 0.f;
    for (int tt = tid; tt < ql; tt += 128) lz += g_logz[b * TQQ + tt];
    red[tid] = lz;
    __syncthreads();
#pragma unroll
    for (int s = 64; s; s >>= 1) {
        if (tid < s) red[tid] += red[tid + s];
        __syncthreads();
    }

    if (tid == 0) {
        float mE = sm_even[kl];     int eE = sm_ex[kl];       // state 2kl
        float mL = sm_odd[kl - 1];  int eL = sm_ex[kl - 1];   // state 2kl-1
        double ll;
        if (mE == 0.f && mL == 0.f) {
            ll = -1e9;
        } else {
            int eM = max(mE > 0.f ? eE : EXNEG, mL > 0.f ? eL : EXNEG);
            double s2 = 0.0;
            if (mE > 0.f) s2 += (double)mE * exp2((double)(eE - eM));
            if (mL > 0.f) s2 += (double)mL * exp2((double)(eL - eM));
            ll = log(s2) + (double)eM * 0.6931471805599453;
        }
        ll -= (double)red[0];          // - sum_t log Z_t
        ll -= (double)(ql - 1);        // undo B = A * e^t rescale
        g_loss[b] = (float)(-ll / (double)kl);

        __threadfence();
        unsigned prev = atomicAdd(&g_ctr, 1u);
        if (prev == BB - 1) {
            g_ctr = 0;
            __threadfence();
            float s = 0.f;
            for (int bb = 0; bb < BB; bb++) s += g_loss[bb];
            out[0] = s / (float)BB;
        }
    }
}

extern "C" void kernel_launch(void* const* d_in, const int* in_sizes, int n_in,
                              void* d_out, int out_size) {
    const float* attn     = (const float*)d_in[0];
    const int*   in_lens  = (const int*)d_in[1];
    const int*   out_lens = (const int*)d_in[2];

    zlog_kernel<<<dim3((TQQ + 7) / 8, BB), 256>>>(attn, in_lens, out_lens);
    dp_kernel<<<BB, 128>>>(attn, in_lens, out_lens, (float*)d_out);
}